// round 5
// baseline (speedup 1.0000x reference)
#include <cuda_runtime.h>
#include <cuda_bf16.h>
#include <math.h>
#include <stdint.h>

// ---------------------------------------------------------------------------
// Multi-Latent Attention — mma.sync bf16x3 GEMMs + bf16x3 mma flash attention
// B=2 S=2048 D=2048 H=16 HKV=4 RQ=1024 RKV=512 DH=192 DR=64 DN=128 DV=128
// ---------------------------------------------------------------------------

#define Bsz   2
#define SEQ   2048
#define DMODEL 2048
#define NH    16
#define NKV   4
#define RQ_   1024
#define RKV_  512
#define DH_   192
#define DR_   64
#define DN_   128
#define DV_   128
#define ROWS  (Bsz*SEQ)          // 4096
#define KVAPAD 640               // kv_a N padded 576 -> 640
#define SCALEQ 0.07216878364870322f   // 1/sqrt(192)

// ----------------------------- scratch (fp32) ------------------------------
__device__ float g_qa [ROWS * RQ_];
__device__ float g_qb [ROWS * (NH*DH_)];
__device__ float g_kva[ROWS * KVAPAD];
__device__ float g_kvb[ROWS * (NKV*(DN_+DV_))];

// ----------------------------- scratch (bf16) -------------------------------
__device__ __nv_bfloat16 g_Xhi [ROWS*DMODEL];
__device__ __nv_bfloat16 g_Xlo [ROWS*DMODEL];
__device__ __nv_bfloat16 g_QAhi[ROWS*RQ_];
__device__ __nv_bfloat16 g_QAlo[ROWS*RQ_];
__device__ __nv_bfloat16 g_KVAhi[ROWS*RKV_];
__device__ __nv_bfloat16 g_KVAlo[ROWS*RKV_];
__device__ __nv_bfloat16 g_AThi[ROWS*(NH*DV_)];
__device__ __nv_bfloat16 g_ATlo[ROWS*(NH*DV_)];
// attention operands, split
__device__ __nv_bfloat16 g_Qhi [Bsz*NH *SEQ*DH_];
__device__ __nv_bfloat16 g_Qlo [Bsz*NH *SEQ*DH_];
__device__ __nv_bfloat16 g_Khi [Bsz*NKV*SEQ*DH_];
__device__ __nv_bfloat16 g_Klo [Bsz*NKV*SEQ*DH_];
__device__ __nv_bfloat16 g_Vhi [Bsz*NKV*SEQ*DV_];
__device__ __nv_bfloat16 g_Vlo [Bsz*NKV*SEQ*DV_];
// transposed weights [N][K] bf16 hi/lo
__device__ __nv_bfloat16 g_Wqa_hi [RQ_ * DMODEL];
__device__ __nv_bfloat16 g_Wqa_lo [RQ_ * DMODEL];
__device__ __nv_bfloat16 g_Wqb_hi [(NH*DH_) * RQ_];
__device__ __nv_bfloat16 g_Wqb_lo [(NH*DH_) * RQ_];
__device__ __nv_bfloat16 g_Wkva_hi[KVAPAD * DMODEL];
__device__ __nv_bfloat16 g_Wkva_lo[KVAPAD * DMODEL];
__device__ __nv_bfloat16 g_Wkvb_hi[(NKV*(DN_+DV_)) * RKV_];
__device__ __nv_bfloat16 g_Wkvb_lo[(NKV*(DN_+DV_)) * RKV_];
__device__ __nv_bfloat16 g_Wo_hi  [DMODEL * (NH*DV_)];
__device__ __nv_bfloat16 g_Wo_lo  [DMODEL * (NH*DV_)];

// ----------------------------- PTX helpers ---------------------------------
__device__ __forceinline__ uint32_t smem_u32(const void* p) {
    uint32_t a;
    asm("{ .reg .u64 t; cvta.to.shared.u64 t, %1; cvt.u32.u64 %0, t; }"
        : "=r"(a) : "l"(p));
    return a;
}
__device__ __forceinline__ void cp16(uint32_t dst, const void* src) {
    asm volatile("cp.async.cg.shared.global [%0], [%1], 16;"
                 :: "r"(dst), "l"(src) : "memory");
}
#define CP_COMMIT() asm volatile("cp.async.commit_group;" ::: "memory")
#define CP_WAIT(n)  asm volatile("cp.async.wait_group %0;" :: "n"(n) : "memory")

__device__ __forceinline__ void ldsm_x4(uint32_t* r, uint32_t addr) {
    asm volatile("ldmatrix.sync.aligned.m8n8.x4.shared.b16 {%0,%1,%2,%3}, [%4];"
                 : "=r"(r[0]), "=r"(r[1]), "=r"(r[2]), "=r"(r[3]) : "r"(addr));
}
__device__ __forceinline__ void ldsm_x4_t(uint32_t* r, uint32_t addr) {
    asm volatile("ldmatrix.sync.aligned.m8n8.x4.trans.shared.b16 {%0,%1,%2,%3}, [%4];"
                 : "=r"(r[0]), "=r"(r[1]), "=r"(r[2]), "=r"(r[3]) : "r"(addr));
}
__device__ __forceinline__ void mma16816(float* c, const uint32_t* a,
                                         uint32_t b0, uint32_t b1) {
    asm volatile(
        "mma.sync.aligned.m16n8k16.row.col.f32.bf16.bf16.f32 "
        "{%0,%1,%2,%3}, {%4,%5,%6,%7}, {%8,%9}, {%0,%1,%2,%3};"
        : "+f"(c[0]), "+f"(c[1]), "+f"(c[2]), "+f"(c[3])
        : "r"(a[0]), "r"(a[1]), "r"(a[2]), "r"(a[3]), "r"(b0), "r"(b1));
}

// ----------------------------- tc GEMM (mma.sync bf16x3, 3-stage) ----------
#define BK    32
#define RSTR  40
#define TILE_H (128*RSTR)
#define STAGE_H (4*TILE_H)
#define TC_SMEM_BYTES (3*STAGE_H*2)     // 122880

__global__ __launch_bounds__(256)
void tc_gemm_bias(int M, int N, int K,
                  const __nv_bfloat16* __restrict__ Ahi,
                  const __nv_bfloat16* __restrict__ Alo,
                  const __nv_bfloat16* __restrict__ Bhi,
                  const __nv_bfloat16* __restrict__ Blo,
                  const float* __restrict__ bias, int nbias,
                  float* __restrict__ C, int ldc)
{
    extern __shared__ __nv_bfloat16 smg[];
    const int tid  = threadIdx.x;
    const int lane = tid & 31;
    const int wid  = tid >> 5;
    const int m0 = blockIdx.y * 128;
    const int n0 = blockIdx.x * 128;
    const int wm = (wid & 3) << 5;
    const int wn = (wid >> 2) << 6;
    const uint32_t sbase = smem_u32(smg);

    const __nv_bfloat16* gsrc[4] = {
        Ahi + (size_t)m0 * K, Alo + (size_t)m0 * K,
        Bhi + (size_t)n0 * K, Blo + (size_t)n0 * K };

    const int lr = tid >> 2;
    const int lc = tid & 3;
    const int nch = K / BK;

    auto load_chunk = [&](int i, int s) {
        const int k0 = i * BK;
        const uint32_t sb = sbase + (uint32_t)s * STAGE_H * 2;
        #pragma unroll
        for (int m = 0; m < 4; ++m) {
            const __nv_bfloat16* g = gsrc[m] + k0;
            const uint32_t sd = sb + m * TILE_H * 2;
            cp16(sd + (lr * RSTR + lc * 8) * 2,        g + (size_t)lr * K + lc * 8);
            cp16(sd + ((lr + 64) * RSTR + lc * 8) * 2, g + (size_t)(lr + 64) * K + lc * 8);
        }
        CP_COMMIT();
    };

    float acc[2][8][4];
    #pragma unroll
    for (int mt = 0; mt < 2; ++mt)
        #pragma unroll
        for (int nt = 0; nt < 8; ++nt)
            #pragma unroll
            for (int j = 0; j < 4; ++j) acc[mt][nt][j] = 0.f;

    load_chunk(0, 0);
    load_chunk(1, 1);

    const int grp = lane >> 3, wi = lane & 7;
    const int a_row = ((grp & 1) << 3) + wi;
    const int a_kof = (grp >> 1) << 3;
    const int b_row = ((grp >> 1) << 3) + wi;
    const int b_kof = (grp & 1) << 3;

    for (int i = 0; i < nch; ++i) {
        if (i + 1 < nch) { CP_WAIT(1); } else { CP_WAIT(0); }
        __syncthreads();
        if (i + 2 < nch) load_chunk(i + 2, (i + 2) % 3);

        const uint32_t sb = sbase + (uint32_t)(i % 3) * STAGE_H * 2;
        const uint32_t sAh = sb;
        const uint32_t sAl = sb + TILE_H * 2;
        const uint32_t sBh = sb + 2 * TILE_H * 2;
        const uint32_t sBl = sb + 3 * TILE_H * 2;

        #pragma unroll
        for (int ks = 0; ks < 2; ++ks) {
            const int k0 = ks << 4;
            uint32_t Ahf[2][4], Alf[2][4], Bhf[4][4], Blf[4][4];
            #pragma unroll
            for (int mt = 0; mt < 2; ++mt) {
                uint32_t off = ((wm + mt * 16 + a_row) * RSTR + k0 + a_kof) * 2;
                ldsm_x4(Ahf[mt], sAh + off);
                ldsm_x4(Alf[mt], sAl + off);
            }
            #pragma unroll
            for (int bt = 0; bt < 4; ++bt) {
                uint32_t off = ((wn + bt * 16 + b_row) * RSTR + k0 + b_kof) * 2;
                ldsm_x4(Bhf[bt], sBh + off);
                ldsm_x4(Blf[bt], sBl + off);
            }
            #pragma unroll
            for (int mt = 0; mt < 2; ++mt)
                #pragma unroll
                for (int bt = 0; bt < 4; ++bt) {
                    mma16816(acc[mt][bt*2+0], Ahf[mt], Bhf[bt][0], Bhf[bt][1]);
                    mma16816(acc[mt][bt*2+1], Ahf[mt], Bhf[bt][2], Bhf[bt][3]);
                    mma16816(acc[mt][bt*2+0], Alf[mt], Bhf[bt][0], Bhf[bt][1]);
                    mma16816(acc[mt][bt*2+1], Alf[mt], Bhf[bt][2], Bhf[bt][3]);
                    mma16816(acc[mt][bt*2+0], Ahf[mt], Blf[bt][0], Blf[bt][1]);
                    mma16816(acc[mt][bt*2+1], Ahf[mt], Blf[bt][2], Blf[bt][3]);
                }
        }
        __syncthreads();
    }

    const int er = lane >> 2;
    const int ec = (lane & 3) * 2;
    #pragma unroll
    for (int mt = 0; mt < 2; ++mt) {
        #pragma unroll
        for (int nt = 0; nt < 8; ++nt) {
            int gm = m0 + wm + mt * 16 + er;
            int gn = n0 + wn + nt * 8 + ec;
            float b0 = (gn     < nbias) ? bias[gn]     : 0.f;
            float b1 = (gn + 1 < nbias) ? bias[gn + 1] : 0.f;
            C[(size_t)gm * ldc + gn]           = acc[mt][nt][0] + b0;
            C[(size_t)gm * ldc + gn + 1]       = acc[mt][nt][1] + b1;
            C[(size_t)(gm + 8) * ldc + gn]     = acc[mt][nt][2] + b0;
            C[(size_t)(gm + 8) * ldc + gn + 1] = acc[mt][nt][3] + b1;
        }
    }
}

// ----------------------------- split / transpose ----------------------------
__global__ __launch_bounds__(256)
void split_kernel(const float* __restrict__ X, int rows, int W, int stride,
                  __nv_bfloat16* __restrict__ hi, __nv_bfloat16* __restrict__ lo)
{
    int idx = blockIdx.x * 256 + threadIdx.x;
    if (idx >= rows * W) return;
    int r = idx / W, c = idx - r * W;
    float v = X[(size_t)r * stride + c];
    __nv_bfloat16 h = __float2bfloat16_rn(v);
    hi[idx] = h;
    lo[idx] = __float2bfloat16_rn(v - __bfloat162float(h));
}

__global__ __launch_bounds__(256)
void transpose_split(const float* __restrict__ W, int K, int N, int /*Npad*/,
                     __nv_bfloat16* __restrict__ Thi, __nv_bfloat16* __restrict__ Tlo)
{
    __shared__ float t[32][33];
    int n0 = blockIdx.x * 32, k0 = blockIdx.y * 32;
    int x = threadIdx.x, y0 = threadIdx.y;
    #pragma unroll
    for (int i = 0; i < 4; ++i) {
        int k = k0 + y0 + i * 8;
        int n = n0 + x;
        t[y0 + i * 8][x] = (n < N) ? W[(size_t)k * N + n] : 0.f;
    }
    __syncthreads();
    #pragma unroll
    for (int i = 0; i < 4; ++i) {
        int n = n0 + y0 + i * 8;
        int k = k0 + x;
        float v = t[x][y0 + i * 8];
        __nv_bfloat16 h = __float2bfloat16_rn(v);
        Thi[(size_t)n * K + k] = h;
        Tlo[(size_t)n * K + k] = __float2bfloat16_rn(v - __bfloat162float(h));
    }
}

// ----------------------------- rmsnorm + split ------------------------------
__global__ __launch_bounds__(256)
void rmsnorm_split(const float* __restrict__ x, const float* __restrict__ g,
                   int W, int stride,
                   __nv_bfloat16* __restrict__ hi, __nv_bfloat16* __restrict__ lo)
{
    __shared__ float warp_s[8];
    int row = blockIdx.x;
    const float* xr = x + (size_t)row * stride;

    float ss = 0.f;
    for (int j = threadIdx.x; j < W; j += 256) { float v = xr[j]; ss = fmaf(v, v, ss); }
    #pragma unroll
    for (int o = 16; o; o >>= 1) ss += __shfl_xor_sync(0xffffffffu, ss, o);
    if ((threadIdx.x & 31) == 0) warp_s[threadIdx.x >> 5] = ss;
    __syncthreads();
    if (threadIdx.x < 8) {
        float v = warp_s[threadIdx.x];
        #pragma unroll
        for (int o = 4; o; o >>= 1) v += __shfl_xor_sync(0xffu, v, o);
        if (threadIdx.x == 0) warp_s[0] = v;
    }
    __syncthreads();
    float inv = rsqrtf(warp_s[0] / (float)W + 1e-20f);
    for (int j = threadIdx.x; j < W; j += 256) {
        float v = xr[j] * inv * g[j];
        __nv_bfloat16 h = __float2bfloat16_rn(v);
        hi[(size_t)row * W + j] = h;
        lo[(size_t)row * W + j] = __float2bfloat16_rn(v - __bfloat162float(h));
    }
}

// ----------------------------- RoPE + split --------------------------------
__device__ __forceinline__ float2 rope_cs(int s, int idx)
{
    float t = (float)(2 * idx) / 64.0f;
    float inv_freq = 1.0f / powf(10000.0f, t);
    float ang = (float)s * inv_freq;
    return make_float2(cosf(ang), sinf(ang));
}

// q_b [4096,H*192] -> Qhi/Qlo [B,H,S,192] ([rope|nrope]) * SCALEQ
__global__ __launch_bounds__(256)
void rope_q_split(const float* __restrict__ qb,
                  __nv_bfloat16* __restrict__ Qhi, __nv_bfloat16* __restrict__ Qlo)
{
    int t = blockIdx.x * 256 + threadIdx.x;
    const int TOTAL = Bsz * NH * SEQ * DH_;
    if (t >= TOTAL) return;
    int j = t % DH_;
    int s = (t / DH_) % SEQ;
    int h = (t / (DH_ * SEQ)) % NH;
    int b = t / (DH_ * SEQ * NH);
    size_t src = ((size_t)(b * SEQ + s)) * (NH * DH_) + h * DH_;
    float val;
    if (j >= DR_) {
        val = qb[src + (j - DR_)];
    } else {
        float x   = qb[src + DN_ + j];
        float rot = (j < 32) ? -qb[src + DN_ + j + 32] : qb[src + DN_ + j - 32];
        int idx = (j < 32) ? j : j - 32;
        float2 cs = rope_cs(s, idx);
        val = x * cs.x + rot * cs.y;
    }
    val *= SCALEQ;                        // fold 1/sqrt(DH)
    __nv_bfloat16 hh = __float2bfloat16_rn(val);
    Qhi[t] = hh;
    Qlo[t] = __float2bfloat16_rn(val - __bfloat162float(hh));
}

// kv_a/kv_b -> Khi/Klo [B,HKV,S,192], Vhi/Vlo [B,HKV,S,128]
__global__ __launch_bounds__(256)
void build_kv_split(const float* __restrict__ kva, const float* __restrict__ kvb,
                    __nv_bfloat16* __restrict__ Khi, __nv_bfloat16* __restrict__ Klo,
                    __nv_bfloat16* __restrict__ Vhi, __nv_bfloat16* __restrict__ Vlo)
{
    int t = blockIdx.x * 256 + threadIdx.x;
    const int PER = DH_ + DV_;
    const int TOTAL = Bsz * NKV * SEQ * PER;
    if (t >= TOTAL) return;
    int j = t % PER;
    int s = (t / PER) % SEQ;
    int g = (t / (PER * SEQ)) % NKV;
    int b = t / (PER * SEQ * NKV);
    size_t rowa = ((size_t)(b * SEQ + s)) * KVAPAD;
    size_t rowb = ((size_t)(b * SEQ + s)) * (NKV * (DN_ + DV_)) + g * (DN_ + DV_);
    if (j < DH_) {
        float val;
        if (j < DR_) {
            float x   = kva[rowa + RKV_ + j];
            float rot = (j < 32) ? -kva[rowa + RKV_ + j + 32] : kva[rowa + RKV_ + j - 32];
            int idx = (j < 32) ? j : j - 32;
            float2 cs = rope_cs(s, idx);
            val = x * cs.x + rot * cs.y;
        } else {
            val = kvb[rowb + (j - DR_)];
        }
        size_t o = (((size_t)(b * NKV + g)) * SEQ + s) * DH_ + j;
        __nv_bfloat16 hh = __float2bfloat16_rn(val);
        Khi[o] = hh;
        Klo[o] = __float2bfloat16_rn(val - __bfloat162float(hh));
    } else {
        float val = kvb[rowb + DN_ + (j - DH_)];
        size_t o = (((size_t)(b * NKV + g)) * SEQ + s) * DV_ + (j - DH_);
        __nv_bfloat16 hh = __float2bfloat16_rn(val);
        Vhi[o] = hh;
        Vlo[o] = __float2bfloat16_rn(val - __bfloat162float(hh));
    }
}

// ----------------------------- mma flash attention --------------------------
// 128 q rows / CTA, 8 warps x m16. K tiles of 64. bf16x3.
// K single-buffered (freed after S), V double-buffered; next-tile loads overlap
// softmax + PV of current tile.
#define ABQ 128
#define ABK 64
#define QSTR 200
#define KSTR 200
#define VSTR 136
#define A_QH 0
#define A_QL 51200
#define A_KH 102400
#define A_KL 128000
#define A_V0 153600
#define VBUF 17408                      // one V matrix (64*136*2)
#define ATTN_SMEM 223232                // A_V0 + 4*VBUF

__global__ __launch_bounds__(256)
void attn_mma(const __nv_bfloat16* __restrict__ Qhg, const __nv_bfloat16* __restrict__ Qlg,
              const __nv_bfloat16* __restrict__ Khg, const __nv_bfloat16* __restrict__ Klg,
              const __nv_bfloat16* __restrict__ Vhg, const __nv_bfloat16* __restrict__ Vlg,
              __nv_bfloat16* __restrict__ Ohi, __nv_bfloat16* __restrict__ Olo)
{
    extern __shared__ __nv_bfloat16 sma[];
    const uint32_t sbase = smem_u32(sma);
    const int tid = threadIdx.x;
    const int lane = tid & 31;
    const int w = tid >> 5;
    const int q0 = blockIdx.x * ABQ;
    const int h  = blockIdx.y;
    const int b  = blockIdx.z;
    const int g  = h >> 2;

    const __nv_bfloat16* Qh = Qhg + (((size_t)(b * NH + h)) * SEQ + q0) * DH_;
    const __nv_bfloat16* Ql = Qlg + (((size_t)(b * NH + h)) * SEQ + q0) * DH_;
    const __nv_bfloat16* Kh = Khg + ((size_t)(b * NKV + g)) * SEQ * DH_;
    const __nv_bfloat16* Kl = Klg + ((size_t)(b * NKV + g)) * SEQ * DH_;
    const __nv_bfloat16* Vh = Vhg + ((size_t)(b * NKV + g)) * SEQ * DV_;
    const __nv_bfloat16* Vl = Vlg + ((size_t)(b * NKV + g)) * SEQ * DV_;

    // prologue loads: Q (both), K0, V0 -> one commit group
    for (int idx = tid; idx < ABQ * 24; idx += 256) {
        int r = idx / 24, c = (idx % 24) * 8;
        cp16(sbase + A_QH + (r * QSTR + c) * 2, Qh + (size_t)r * DH_ + c);
        cp16(sbase + A_QL + (r * QSTR + c) * 2, Ql + (size_t)r * DH_ + c);
    }
    for (int idx = tid; idx < ABK * 24; idx += 256) {
        int r = idx / 24, c = (idx % 24) * 8;
        cp16(sbase + A_KH + (r * KSTR + c) * 2, Kh + (size_t)r * DH_ + c);
        cp16(sbase + A_KL + (r * KSTR + c) * 2, Kl + (size_t)r * DH_ + c);
    }
    for (int idx = tid; idx < ABK * 16; idx += 256) {
        int r = idx >> 4, c = (idx & 15) * 8;
        cp16(sbase + A_V0 + (r * VSTR + c) * 2,        Vh + (size_t)r * DV_ + c);
        cp16(sbase + A_V0 + VBUF + (r * VSTR + c) * 2, Vl + (size_t)r * DV_ + c);
    }
    CP_COMMIT();

    const int grp = lane >> 3, wi = lane & 7;
    const int a_row = ((grp & 1) << 3) + wi;
    const int a_kof = (grp >> 1) << 3;
    const int b_row = ((grp >> 1) << 3) + wi;
    const int b_kof = (grp & 1) << 3;
    const int q0w = q0 + w * 16;
    const int r_in = lane >> 2;
    const int c2   = (lane & 3) * 2;

    float o[16][4];
    #pragma unroll
    for (int i = 0; i < 16; ++i)
        #pragma unroll
        for (int j = 0; j < 4; ++j) o[i][j] = 0.f;
    float m0r = -INFINITY, m1r = -INFINITY, l0 = 0.f, l1 = 0.f;

    const int ntiles = (q0 + ABQ) / ABK;
    for (int t = 0; t < ntiles; ++t) {
        const int ks = t * ABK;
        const bool active = (ks <= q0w + 15);
        CP_WAIT(0);
        __syncthreads();

        // ---- S = Qh*Kh + Ql*Kh + Qh*Kl (scale pre-folded into Q) ----
        float s[8][4];
        if (active) {
            #pragma unroll
            for (int i = 0; i < 8; ++i)
                #pragma unroll
                for (int j = 0; j < 4; ++j) s[i][j] = 0.f;
            #pragma unroll
            for (int kst = 0; kst < 12; ++kst) {
                uint32_t qh[4], ql[4];
                uint32_t qoff = ((w * 16 + a_row) * QSTR + kst * 16 + a_kof) * 2;
                ldsm_x4(qh, sbase + A_QH + qoff);
                ldsm_x4(ql, sbase + A_QL + qoff);
                #pragma unroll
                for (int np = 0; np < 4; ++np) {
                    uint32_t kh[4], kl[4];
                    uint32_t koff = ((np * 16 + b_row) * KSTR + kst * 16 + b_kof) * 2;
                    ldsm_x4(kh, sbase + A_KH + koff);
                    ldsm_x4(kl, sbase + A_KL + koff);
                    mma16816(s[np*2+0], qh, kh[0], kh[1]);
                    mma16816(s[np*2+1], qh, kh[2], kh[3]);
                    mma16816(s[np*2+0], ql, kh[0], kh[1]);
                    mma16816(s[np*2+1], ql, kh[2], kh[3]);
                    mma16816(s[np*2+0], qh, kl[0], kl[1]);
                    mma16816(s[np*2+1], qh, kl[2], kl[3]);
                }
            }
        }
        __syncthreads();   // all warps done reading K (and prior-stage V)

        // ---- prefetch next tile (K single, V stage (t+1)&1) ----
        if (t + 1 < ntiles) {
            const int ks2 = ks + ABK;
            for (int idx = tid; idx < ABK * 24; idx += 256) {
                int r = idx / 24, c = (idx % 24) * 8;
                cp16(sbase + A_KH + (r * KSTR + c) * 2, Kh + (size_t)(ks2 + r) * DH_ + c);
                cp16(sbase + A_KL + (r * KSTR + c) * 2, Kl + (size_t)(ks2 + r) * DH_ + c);
            }
            const uint32_t vb = sbase + A_V0 + (uint32_t)((t + 1) & 1) * 2 * VBUF;
            for (int idx = tid; idx < ABK * 16; idx += 256) {
                int r = idx >> 4, c = (idx & 15) * 8;
                cp16(vb + (r * VSTR + c) * 2,        Vh + (size_t)(ks2 + r) * DV_ + c);
                cp16(vb + VBUF + (r * VSTR + c) * 2, Vl + (size_t)(ks2 + r) * DV_ + c);
            }
            CP_COMMIT();
        }

        if (active) {
            // ---- mask + row max ----
            const int row0 = q0w + r_in;
            float tm0 = -INFINITY, tm1 = -INFINITY;
            #pragma unroll
            for (int nt = 0; nt < 8; ++nt) {
                #pragma unroll
                for (int e = 0; e < 2; ++e) {
                    int col = ks + nt * 8 + c2 + e;
                    s[nt][e]     = (col <= row0)     ? s[nt][e]     : -INFINITY;
                    s[nt][e + 2] = (col <= row0 + 8) ? s[nt][e + 2] : -INFINITY;
                    tm0 = fmaxf(tm0, s[nt][e]);
                    tm1 = fmaxf(tm1, s[nt][e + 2]);
                }
            }
            tm0 = fmaxf(tm0, __shfl_xor_sync(0xffffffffu, tm0, 1));
            tm0 = fmaxf(tm0, __shfl_xor_sync(0xffffffffu, tm0, 2));
            tm1 = fmaxf(tm1, __shfl_xor_sync(0xffffffffu, tm1, 1));
            tm1 = fmaxf(tm1, __shfl_xor_sync(0xffffffffu, tm1, 2));
            float mn0 = fmaxf(m0r, tm0), mn1 = fmaxf(m1r, tm1);
            float al0 = __expf(m0r - mn0), al1 = __expf(m1r - mn1);
            m0r = mn0; m1r = mn1;

            // ---- P = exp(S - m), split hi/lo ----
            uint32_t pah[4][4], pal[4][4];
            float ps0 = 0.f, ps1 = 0.f;
            #pragma unroll
            for (int kc = 0; kc < 4; ++kc) {
                #pragma unroll
                for (int half = 0; half < 2; ++half) {
                    float* f = s[kc * 2 + half];
                    float p0 = __expf(f[0] - mn0), p1 = __expf(f[1] - mn0);
                    float p2 = __expf(f[2] - mn1), p3 = __expf(f[3] - mn1);
                    ps0 += p0 + p1; ps1 += p2 + p3;
                    __nv_bfloat162 h01 = __floats2bfloat162_rn(p0, p1);
                    __nv_bfloat162 h23 = __floats2bfloat162_rn(p2, p3);
                    float r0 = p0 - __bfloat162float(h01.x);
                    float r1 = p1 - __bfloat162float(h01.y);
                    float r2 = p2 - __bfloat162float(h23.x);
                    float r3 = p3 - __bfloat162float(h23.y);
                    __nv_bfloat162 l01 = __floats2bfloat162_rn(r0, r1);
                    __nv_bfloat162 l23 = __floats2bfloat162_rn(r2, r3);
                    pah[kc][half * 2 + 0] = *reinterpret_cast<uint32_t*>(&h01);
                    pah[kc][half * 2 + 1] = *reinterpret_cast<uint32_t*>(&h23);
                    pal[kc][half * 2 + 0] = *reinterpret_cast<uint32_t*>(&l01);
                    pal[kc][half * 2 + 1] = *reinterpret_cast<uint32_t*>(&l23);
                }
            }
            l0 = l0 * al0 + ps0;
            l1 = l1 * al1 + ps1;

            // ---- rescale O, then O += Ph*Vh + Pl*Vh + Ph*Vl ----
            #pragma unroll
            for (int nt = 0; nt < 16; ++nt) {
                o[nt][0] *= al0; o[nt][1] *= al0;
                o[nt][2] *= al1; o[nt][3] *= al1;
            }
            const uint32_t vb = sbase + A_V0 + (uint32_t)(t & 1) * 2 * VBUF;
            #pragma unroll
            for (int kc = 0; kc < 4; ++kc) {
                #pragma unroll
                for (int np = 0; np < 8; ++np) {
                    uint32_t vh[4], vl[4];
                    uint32_t voff = ((kc * 16 + ((grp & 1) << 3) + wi) * VSTR
                                     + np * 16 + ((grp >> 1) << 3)) * 2;
                    ldsm_x4_t(vh, vb + voff);
                    ldsm_x4_t(vl, vb + VBUF + voff);
                    mma16816(o[np*2+0], pah[kc], vh[0], vh[1]);
                    mma16816(o[np*2+1], pah[kc], vh[2], vh[3]);
                    mma16816(o[np*2+0], pal[kc], vh[0], vh[1]);
                    mma16816(o[np*2+1], pal[kc], vh[2], vh[3]);
                    mma16816(o[np*2+0], pah[kc], vl[0], vl[1]);
                    mma16816(o[np*2+1], pah[kc], vl[2], vl[3]);
                }
            }
        }
    }

    // final normalize + write hi/lo bf16
    l0 += __shfl_xor_sync(0xffffffffu, l0, 1);
    l0 += __shfl_xor_sync(0xffffffffu, l0, 2);
    l1 += __shfl_xor_sync(0xffffffffu, l1, 1);
    l1 += __shfl_xor_sync(0xffffffffu, l1, 2);
    float inv0 = 1.0f / l0, inv1 = 1.0f / l1;

    const size_t row0 = (size_t)(b * SEQ + q0w + r_in) * (NH * DV_);
    const size_t row1 = row0 + 8 * (NH * DV_);
    #pragma unroll
    for (int np = 0; np < 16; ++np) {
        int col = h * DV_ + np * 8 + c2;
        float v0 = o[np][0] * inv0, v1 = o[np][1] * inv0;
        float v2 = o[np][2] * inv1, v3 = o[np][3] * inv1;
        __nv_bfloat162 h01 = __floats2bfloat162_rn(v0, v1);
        __nv_bfloat162 h23 = __floats2bfloat162_rn(v2, v3);
        __nv_bfloat162 l01 = __floats2bfloat162_rn(v0 - __bfloat162float(h01.x),
                                                   v1 - __bfloat162float(h01.y));
        __nv_bfloat162 l23 = __floats2bfloat162_rn(v2 - __bfloat162float(h23.x),
                                                   v3 - __bfloat162float(h23.y));
        *reinterpret_cast<__nv_bfloat162*>(&Ohi[row0 + col]) = h01;
        *reinterpret_cast<__nv_bfloat162*>(&Ohi[row1 + col]) = h23;
        *reinterpret_cast<__nv_bfloat162*>(&Olo[row0 + col]) = l01;
        *reinterpret_cast<__nv_bfloat162*>(&Olo[row1 + col]) = l23;
    }
}

// ----------------------------- host ----------------------------------------
extern "C" void kernel_launch(void* const* d_in, const int* in_sizes, int n_in,
                              void* d_out, int out_size)
{
    const float* X     = (const float*)d_in[0];
    const float* w_qa  = (const float*)d_in[2];
    const float* b_qa  = (const float*)d_in[3];
    const float* gq    = (const float*)d_in[4];
    const float* w_qb  = (const float*)d_in[5];
    const float* b_qb  = (const float*)d_in[6];
    const float* w_kva = (const float*)d_in[7];
    const float* b_kva = (const float*)d_in[8];
    const float* gkv   = (const float*)d_in[9];
    const float* w_kvb = (const float*)d_in[10];
    const float* b_kvb = (const float*)d_in[11];
    const float* w_o   = (const float*)d_in[12];
    const float* b_o   = (const float*)d_in[13];
    float* out = (float*)d_out;

    float *qa, *qb, *kva, *kvb;
    cudaGetSymbolAddress((void**)&qa,  g_qa);
    cudaGetSymbolAddress((void**)&qb,  g_qb);
    cudaGetSymbolAddress((void**)&kva, g_kva);
    cudaGetSymbolAddress((void**)&kvb, g_kvb);

    __nv_bfloat16 *Xhi, *Xlo, *QAhi, *QAlo, *KVAhi, *KVAlo, *AThi, *ATlo;
    __nv_bfloat16 *Qhi, *Qlo, *Khi, *Klo, *Vhi, *Vlo;
    __nv_bfloat16 *Wqah, *Wqal, *Wqbh, *Wqbl, *Wkvah, *Wkval, *Wkvbh, *Wkvbl, *Woh, *Wol;
    cudaGetSymbolAddress((void**)&Xhi,  g_Xhi);
    cudaGetSymbolAddress((void**)&Xlo,  g_Xlo);
    cudaGetSymbolAddress((void**)&QAhi, g_QAhi);
    cudaGetSymbolAddress((void**)&QAlo, g_QAlo);
    cudaGetSymbolAddress((void**)&KVAhi,g_KVAhi);
    cudaGetSymbolAddress((void**)&KVAlo,g_KVAlo);
    cudaGetSymbolAddress((void**)&AThi, g_AThi);
    cudaGetSymbolAddress((void**)&ATlo, g_ATlo);
    cudaGetSymbolAddress((void**)&Qhi,  g_Qhi);
    cudaGetSymbolAddress((void**)&Qlo,  g_Qlo);
    cudaGetSymbolAddress((void**)&Khi,  g_Khi);
    cudaGetSymbolAddress((void**)&Klo,  g_Klo);
    cudaGetSymbolAddress((void**)&Vhi,  g_Vhi);
    cudaGetSymbolAddress((void**)&Vlo,  g_Vlo);
    cudaGetSymbolAddress((void**)&Wqah, g_Wqa_hi);
    cudaGetSymbolAddress((void**)&Wqal, g_Wqa_lo);
    cudaGetSymbolAddress((void**)&Wqbh, g_Wqb_hi);
    cudaGetSymbolAddress((void**)&Wqbl, g_Wqb_lo);
    cudaGetSymbolAddress((void**)&Wkvah,g_Wkva_hi);
    cudaGetSymbolAddress((void**)&Wkval,g_Wkva_lo);
    cudaGetSymbolAddress((void**)&Wkvbh,g_Wkvb_hi);
    cudaGetSymbolAddress((void**)&Wkvbl,g_Wkvb_lo);
    cudaGetSymbolAddress((void**)&Woh,  g_Wo_hi);
    cudaGetSymbolAddress((void**)&Wol,  g_Wo_lo);

    cudaFuncSetAttribute(tc_gemm_bias,
        cudaFuncAttributeMaxDynamicSharedMemorySize, TC_SMEM_BYTES);
    cudaFuncSetAttribute(attn_mma,
        cudaFuncAttributeMaxDynamicSharedMemorySize, ATTN_SMEM);

    dim3 tpb(32, 8);

    // weight prep
    transpose_split<<<dim3(RQ_/32, DMODEL/32), tpb>>>(w_qa, DMODEL, RQ_, RQ_, Wqah, Wqal);
    transpose_split<<<dim3((NH*DH_)/32, RQ_/32), tpb>>>(w_qb, RQ_, NH*DH_, NH*DH_, Wqbh, Wqbl);
    transpose_split<<<dim3(KVAPAD/32, DMODEL/32), tpb>>>(w_kva, DMODEL, RKV_+DR_, KVAPAD, Wkvah, Wkval);
    transpose_split<<<dim3((NKV*(DN_+DV_))/32, RKV_/32), tpb>>>(w_kvb, RKV_, NKV*(DN_+DV_), NKV*(DN_+DV_), Wkvbh, Wkvbl);
    transpose_split<<<dim3(DMODEL/32, (NH*DV_)/32), tpb>>>(w_o, NH*DV_, DMODEL, DMODEL, Woh, Wol);

    // X split
    split_kernel<<<(ROWS*DMODEL + 255)/256, 256>>>(X, ROWS, DMODEL, DMODEL, Xhi, Xlo);

    // q path
    tc_gemm_bias<<<dim3(RQ_/128, ROWS/128), 256, TC_SMEM_BYTES>>>(
        ROWS, RQ_, DMODEL, Xhi, Xlo, Wqah, Wqal, b_qa, RQ_, qa, RQ_);
    rmsnorm_split<<<ROWS, 256>>>(qa, gq, RQ_, RQ_, QAhi, QAlo);
    tc_gemm_bias<<<dim3((NH*DH_)/128, ROWS/128), 256, TC_SMEM_BYTES>>>(
        ROWS, NH*DH_, RQ_, QAhi, QAlo, Wqbh, Wqbl, b_qb, NH*DH_, qb, NH*DH_);

    // kv path
    tc_gemm_bias<<<dim3(KVAPAD/128, ROWS/128), 256, TC_SMEM_BYTES>>>(
        ROWS, KVAPAD, DMODEL, Xhi, Xlo, Wkvah, Wkval, b_kva, RKV_+DR_, kva, KVAPAD);
    rmsnorm_split<<<ROWS, 256>>>(kva, gkv, RKV_, KVAPAD, KVAhi, KVAlo);
    tc_gemm_bias<<<dim3((NKV*(DN_+DV_))/128, ROWS/128), 256, TC_SMEM_BYTES>>>(
        ROWS, NKV*(DN_+DV_), RKV_, KVAhi, KVAlo, Wkvbh, Wkvbl, b_kvb, NKV*(DN_+DV_), kvb, NKV*(DN_+DV_));

    // rope + layout (bf16 split outputs)
    {
        int n1 = Bsz*NH*SEQ*DH_;
        rope_q_split<<<(n1 + 255)/256, 256>>>(qb, Qhi, Qlo);
        int n2 = Bsz*NKV*SEQ*(DH_+DV_);
        build_kv_split<<<(n2 + 255)/256, 256>>>(kva, kvb, Khi, Klo, Vhi, Vlo);
    }

    // attention
    attn_mma<<<dim3(SEQ/ABQ, NH, Bsz), 256, ATTN_SMEM>>>(
        Qhi, Qlo, Khi, Klo, Vhi, Vlo, AThi, ATlo);

    // out projection
    tc_gemm_bias<<<dim3(DMODEL/128, ROWS/128), 256, TC_SMEM_BYTES>>>(
        ROWS, DMODEL, NH*DV_, AThi, ATlo, Woh, Wol, b_o, DMODEL, out, DMODEL);
}

// round 6
// speedup vs baseline: 1.1054x; 1.1054x over previous
#include <cuda_runtime.h>
#include <cuda_bf16.h>
#include <math.h>
#include <stdint.h>

// ---------------------------------------------------------------------------
// Multi-Latent Attention — mma.sync bf16x3 GEMMs + bf16x3 mma flash attention
// B=2 S=2048 D=2048 H=16 HKV=4 RQ=1024 RKV=512 DH=192 DR=64 DN=128 DV=128
// ---------------------------------------------------------------------------

#define Bsz   2
#define SEQ   2048
#define DMODEL 2048
#define NH    16
#define NKV   4
#define RQ_   1024
#define RKV_  512
#define DH_   192
#define DR_   64
#define DN_   128
#define DV_   128
#define ROWS  (Bsz*SEQ)          // 4096
#define KVAPAD 640               // kv_a N padded 576 -> 640
#define SCALEQ 0.07216878364870322f   // 1/sqrt(192)

// ----------------------------- scratch (fp32) ------------------------------
__device__ float g_qa [ROWS * RQ_];
__device__ float g_qb [ROWS * (NH*DH_)];
__device__ float g_kva[ROWS * KVAPAD];
__device__ float g_kvb[ROWS * (NKV*(DN_+DV_))];

// ----------------------------- scratch (bf16) -------------------------------
__device__ __nv_bfloat16 g_Xhi [ROWS*DMODEL];
__device__ __nv_bfloat16 g_Xlo [ROWS*DMODEL];
__device__ __nv_bfloat16 g_QAhi[ROWS*RQ_];
__device__ __nv_bfloat16 g_QAlo[ROWS*RQ_];
__device__ __nv_bfloat16 g_KVAhi[ROWS*RKV_];
__device__ __nv_bfloat16 g_KVAlo[ROWS*RKV_];
__device__ __nv_bfloat16 g_AThi[ROWS*(NH*DV_)];
__device__ __nv_bfloat16 g_ATlo[ROWS*(NH*DV_)];
// attention operands, split
__device__ __nv_bfloat16 g_Qhi [Bsz*NH *SEQ*DH_];
__device__ __nv_bfloat16 g_Qlo [Bsz*NH *SEQ*DH_];
__device__ __nv_bfloat16 g_Khi [Bsz*NKV*SEQ*DH_];
__device__ __nv_bfloat16 g_Klo [Bsz*NKV*SEQ*DH_];
__device__ __nv_bfloat16 g_Vhi [Bsz*NKV*SEQ*DV_];
__device__ __nv_bfloat16 g_Vlo [Bsz*NKV*SEQ*DV_];
// transposed weights [N][K] bf16 hi/lo
__device__ __nv_bfloat16 g_Wqa_hi [RQ_ * DMODEL];
__device__ __nv_bfloat16 g_Wqa_lo [RQ_ * DMODEL];
__device__ __nv_bfloat16 g_Wqb_hi [(NH*DH_) * RQ_];
__device__ __nv_bfloat16 g_Wqb_lo [(NH*DH_) * RQ_];
__device__ __nv_bfloat16 g_Wkva_hi[KVAPAD * DMODEL];
__device__ __nv_bfloat16 g_Wkva_lo[KVAPAD * DMODEL];
__device__ __nv_bfloat16 g_Wkvb_hi[(NKV*(DN_+DV_)) * RKV_];
__device__ __nv_bfloat16 g_Wkvb_lo[(NKV*(DN_+DV_)) * RKV_];
__device__ __nv_bfloat16 g_Wo_hi  [DMODEL * (NH*DV_)];
__device__ __nv_bfloat16 g_Wo_lo  [DMODEL * (NH*DV_)];

// ----------------------------- PTX helpers ---------------------------------
__device__ __forceinline__ uint32_t smem_u32(const void* p) {
    uint32_t a;
    asm("{ .reg .u64 t; cvta.to.shared.u64 t, %1; cvt.u32.u64 %0, t; }"
        : "=r"(a) : "l"(p));
    return a;
}
__device__ __forceinline__ void cp16(uint32_t dst, const void* src) {
    asm volatile("cp.async.cg.shared.global [%0], [%1], 16;"
                 :: "r"(dst), "l"(src) : "memory");
}
#define CP_COMMIT() asm volatile("cp.async.commit_group;" ::: "memory")
#define CP_WAIT(n)  asm volatile("cp.async.wait_group %0;" :: "n"(n) : "memory")

__device__ __forceinline__ void ldsm_x4(uint32_t* r, uint32_t addr) {
    asm volatile("ldmatrix.sync.aligned.m8n8.x4.shared.b16 {%0,%1,%2,%3}, [%4];"
                 : "=r"(r[0]), "=r"(r[1]), "=r"(r[2]), "=r"(r[3]) : "r"(addr));
}
__device__ __forceinline__ void ldsm_x4_t(uint32_t* r, uint32_t addr) {
    asm volatile("ldmatrix.sync.aligned.m8n8.x4.trans.shared.b16 {%0,%1,%2,%3}, [%4];"
                 : "=r"(r[0]), "=r"(r[1]), "=r"(r[2]), "=r"(r[3]) : "r"(addr));
}
__device__ __forceinline__ void mma16816(float* c, const uint32_t* a,
                                         uint32_t b0, uint32_t b1) {
    asm volatile(
        "mma.sync.aligned.m16n8k16.row.col.f32.bf16.bf16.f32 "
        "{%0,%1,%2,%3}, {%4,%5,%6,%7}, {%8,%9}, {%0,%1,%2,%3};"
        : "+f"(c[0]), "+f"(c[1]), "+f"(c[2]), "+f"(c[3])
        : "r"(a[0]), "r"(a[1]), "r"(a[2]), "r"(a[3]), "r"(b0), "r"(b1));
}

// ----------------------------- tc GEMM (mma.sync bf16x3, 2-stage) ----------
#define BK    32
#define RSTR  40
#define TILE_H (128*RSTR)
#define STAGE_H (4*TILE_H)
#define TC_SMEM_BYTES (2*STAGE_H*2)    // 81920

__global__ __launch_bounds__(256)
void tc_gemm_bias(int M, int N, int K,
                  const __nv_bfloat16* __restrict__ Ahi,
                  const __nv_bfloat16* __restrict__ Alo,
                  const __nv_bfloat16* __restrict__ Bhi,
                  const __nv_bfloat16* __restrict__ Blo,
                  const float* __restrict__ bias, int nbias,
                  float* __restrict__ C, int ldc)
{
    extern __shared__ __nv_bfloat16 smg[];
    const int tid  = threadIdx.x;
    const int lane = tid & 31;
    const int wid  = tid >> 5;
    const int m0 = blockIdx.y * 128;
    const int n0 = blockIdx.x * 128;
    const int wm = (wid & 3) << 5;
    const int wn = (wid >> 2) << 6;
    const uint32_t sbase = smem_u32(smg);

    const __nv_bfloat16* gsrc[4] = {
        Ahi + (size_t)m0 * K, Alo + (size_t)m0 * K,
        Bhi + (size_t)n0 * K, Blo + (size_t)n0 * K };

    const int lr = tid >> 2;
    const int lc = tid & 3;
    const int nch = K / BK;

    auto load_chunk = [&](int i, int s) {
        const int k0 = i * BK;
        const uint32_t sb = sbase + (uint32_t)s * STAGE_H * 2;
        #pragma unroll
        for (int m = 0; m < 4; ++m) {
            const __nv_bfloat16* g = gsrc[m] + k0;
            const uint32_t sd = sb + m * TILE_H * 2;
            cp16(sd + (lr * RSTR + lc * 8) * 2,        g + (size_t)lr * K + lc * 8);
            cp16(sd + ((lr + 64) * RSTR + lc * 8) * 2, g + (size_t)(lr + 64) * K + lc * 8);
        }
        CP_COMMIT();
    };

    float acc[2][8][4];
    #pragma unroll
    for (int mt = 0; mt < 2; ++mt)
        #pragma unroll
        for (int nt = 0; nt < 8; ++nt)
            #pragma unroll
            for (int j = 0; j < 4; ++j) acc[mt][nt][j] = 0.f;

    load_chunk(0, 0);

    const int grp = lane >> 3, wi = lane & 7;
    const int a_row = ((grp & 1) << 3) + wi;
    const int a_kof = (grp >> 1) << 3;
    const int b_row = ((grp >> 1) << 3) + wi;
    const int b_kof = (grp & 1) << 3;

    for (int i = 0; i < nch; ++i) {
        if (i + 1 < nch) load_chunk(i + 1, (i + 1) & 1);
        if (i + 1 < nch) { CP_WAIT(1); } else { CP_WAIT(0); }
        __syncthreads();

        const uint32_t sb = sbase + (uint32_t)(i & 1) * STAGE_H * 2;
        const uint32_t sAh = sb;
        const uint32_t sAl = sb + TILE_H * 2;
        const uint32_t sBh = sb + 2 * TILE_H * 2;
        const uint32_t sBl = sb + 3 * TILE_H * 2;

        #pragma unroll
        for (int ks = 0; ks < 2; ++ks) {
            const int k0 = ks << 4;
            uint32_t Ahf[2][4], Alf[2][4], Bhf[4][4], Blf[4][4];
            #pragma unroll
            for (int mt = 0; mt < 2; ++mt) {
                uint32_t off = ((wm + mt * 16 + a_row) * RSTR + k0 + a_kof) * 2;
                ldsm_x4(Ahf[mt], sAh + off);
                ldsm_x4(Alf[mt], sAl + off);
            }
            #pragma unroll
            for (int bt = 0; bt < 4; ++bt) {
                uint32_t off = ((wn + bt * 16 + b_row) * RSTR + k0 + b_kof) * 2;
                ldsm_x4(Bhf[bt], sBh + off);
                ldsm_x4(Blf[bt], sBl + off);
            }
            #pragma unroll
            for (int mt = 0; mt < 2; ++mt)
                #pragma unroll
                for (int bt = 0; bt < 4; ++bt) {
                    mma16816(acc[mt][bt*2+0], Ahf[mt], Bhf[bt][0], Bhf[bt][1]);
                    mma16816(acc[mt][bt*2+1], Ahf[mt], Bhf[bt][2], Bhf[bt][3]);
                    mma16816(acc[mt][bt*2+0], Alf[mt], Bhf[bt][0], Bhf[bt][1]);
                    mma16816(acc[mt][bt*2+1], Alf[mt], Bhf[bt][2], Bhf[bt][3]);
                    mma16816(acc[mt][bt*2+0], Ahf[mt], Blf[bt][0], Blf[bt][1]);
                    mma16816(acc[mt][bt*2+1], Ahf[mt], Blf[bt][2], Blf[bt][3]);
                }
        }
        __syncthreads();
    }

    const int er = lane >> 2;
    const int ec = (lane & 3) * 2;
    #pragma unroll
    for (int mt = 0; mt < 2; ++mt) {
        #pragma unroll
        for (int nt = 0; nt < 8; ++nt) {
            int gm = m0 + wm + mt * 16 + er;
            int gn = n0 + wn + nt * 8 + ec;
            float b0 = (gn     < nbias) ? bias[gn]     : 0.f;
            float b1 = (gn + 1 < nbias) ? bias[gn + 1] : 0.f;
            C[(size_t)gm * ldc + gn]           = acc[mt][nt][0] + b0;
            C[(size_t)gm * ldc + gn + 1]       = acc[mt][nt][1] + b1;
            C[(size_t)(gm + 8) * ldc + gn]     = acc[mt][nt][2] + b0;
            C[(size_t)(gm + 8) * ldc + gn + 1] = acc[mt][nt][3] + b1;
        }
    }
}

// ----------------------------- split / transpose ----------------------------
__global__ __launch_bounds__(256)
void split_kernel(const float* __restrict__ X, int rows, int W, int stride,
                  __nv_bfloat16* __restrict__ hi, __nv_bfloat16* __restrict__ lo)
{
    int idx = blockIdx.x * 256 + threadIdx.x;
    if (idx >= rows * W) return;
    int r = idx / W, c = idx - r * W;
    float v = X[(size_t)r * stride + c];
    __nv_bfloat16 h = __float2bfloat16_rn(v);
    hi[idx] = h;
    lo[idx] = __float2bfloat16_rn(v - __bfloat162float(h));
}

__global__ __launch_bounds__(256)
void transpose_split(const float* __restrict__ W, int K, int N, int /*Npad*/,
                     __nv_bfloat16* __restrict__ Thi, __nv_bfloat16* __restrict__ Tlo)
{
    __shared__ float t[32][33];
    int n0 = blockIdx.x * 32, k0 = blockIdx.y * 32;
    int x = threadIdx.x, y0 = threadIdx.y;
    #pragma unroll
    for (int i = 0; i < 4; ++i) {
        int k = k0 + y0 + i * 8;
        int n = n0 + x;
        t[y0 + i * 8][x] = (n < N) ? W[(size_t)k * N + n] : 0.f;
    }
    __syncthreads();
    #pragma unroll
    for (int i = 0; i < 4; ++i) {
        int n = n0 + y0 + i * 8;
        int k = k0 + x;
        float v = t[x][y0 + i * 8];
        __nv_bfloat16 h = __float2bfloat16_rn(v);
        Thi[(size_t)n * K + k] = h;
        Tlo[(size_t)n * K + k] = __float2bfloat16_rn(v - __bfloat162float(h));
    }
}

// ----------------------------- rmsnorm + split ------------------------------
__global__ __launch_bounds__(256)
void rmsnorm_split(const float* __restrict__ x, const float* __restrict__ g,
                   int W, int stride,
                   __nv_bfloat16* __restrict__ hi, __nv_bfloat16* __restrict__ lo)
{
    __shared__ float warp_s[8];
    int row = blockIdx.x;
    const float* xr = x + (size_t)row * stride;

    float ss = 0.f;
    for (int j = threadIdx.x; j < W; j += 256) { float v = xr[j]; ss = fmaf(v, v, ss); }
    #pragma unroll
    for (int o = 16; o; o >>= 1) ss += __shfl_xor_sync(0xffffffffu, ss, o);
    if ((threadIdx.x & 31) == 0) warp_s[threadIdx.x >> 5] = ss;
    __syncthreads();
    if (threadIdx.x < 8) {
        float v = warp_s[threadIdx.x];
        #pragma unroll
        for (int o = 4; o; o >>= 1) v += __shfl_xor_sync(0xffu, v, o);
        if (threadIdx.x == 0) warp_s[0] = v;
    }
    __syncthreads();
    float inv = rsqrtf(warp_s[0] / (float)W + 1e-20f);
    for (int j = threadIdx.x; j < W; j += 256) {
        float v = xr[j] * inv * g[j];
        __nv_bfloat16 h = __float2bfloat16_rn(v);
        hi[(size_t)row * W + j] = h;
        lo[(size_t)row * W + j] = __float2bfloat16_rn(v - __bfloat162float(h));
    }
}

// ----------------------------- RoPE + split --------------------------------
__device__ __forceinline__ float2 rope_cs(int s, int idx)
{
    float t = (float)(2 * idx) / 64.0f;
    float inv_freq = 1.0f / powf(10000.0f, t);
    float ang = (float)s * inv_freq;
    return make_float2(cosf(ang), sinf(ang));
}

// q_b [4096,H*192] -> Qhi/Qlo [B,H,S,192] ([rope|nrope]) * SCALEQ
__global__ __launch_bounds__(256)
void rope_q_split(const float* __restrict__ qb,
                  __nv_bfloat16* __restrict__ Qhi, __nv_bfloat16* __restrict__ Qlo)
{
    int t = blockIdx.x * 256 + threadIdx.x;
    const int TOTAL = Bsz * NH * SEQ * DH_;
    if (t >= TOTAL) return;
    int j = t % DH_;
    int s = (t / DH_) % SEQ;
    int h = (t / (DH_ * SEQ)) % NH;
    int b = t / (DH_ * SEQ * NH);
    size_t src = ((size_t)(b * SEQ + s)) * (NH * DH_) + h * DH_;
    float val;
    if (j >= DR_) {
        val = qb[src + (j - DR_)];
    } else {
        float x   = qb[src + DN_ + j];
        float rot = (j < 32) ? -qb[src + DN_ + j + 32] : qb[src + DN_ + j - 32];
        int idx = (j < 32) ? j : j - 32;
        float2 cs = rope_cs(s, idx);
        val = x * cs.x + rot * cs.y;
    }
    val *= SCALEQ;                        // fold 1/sqrt(DH)
    __nv_bfloat16 hh = __float2bfloat16_rn(val);
    Qhi[t] = hh;
    Qlo[t] = __float2bfloat16_rn(val - __bfloat162float(hh));
}

// kv_a/kv_b -> Khi/Klo [B,HKV,S,192], Vhi/Vlo [B,HKV,S,128]
__global__ __launch_bounds__(256)
void build_kv_split(const float* __restrict__ kva, const float* __restrict__ kvb,
                    __nv_bfloat16* __restrict__ Khi, __nv_bfloat16* __restrict__ Klo,
                    __nv_bfloat16* __restrict__ Vhi, __nv_bfloat16* __restrict__ Vlo)
{
    int t = blockIdx.x * 256 + threadIdx.x;
    const int PER = DH_ + DV_;
    const int TOTAL = Bsz * NKV * SEQ * PER;
    if (t >= TOTAL) return;
    int j = t % PER;
    int s = (t / PER) % SEQ;
    int g = (t / (PER * SEQ)) % NKV;
    int b = t / (PER * SEQ * NKV);
    size_t rowa = ((size_t)(b * SEQ + s)) * KVAPAD;
    size_t rowb = ((size_t)(b * SEQ + s)) * (NKV * (DN_ + DV_)) + g * (DN_ + DV_);
    if (j < DH_) {
        float val;
        if (j < DR_) {
            float x   = kva[rowa + RKV_ + j];
            float rot = (j < 32) ? -kva[rowa + RKV_ + j + 32] : kva[rowa + RKV_ + j - 32];
            int idx = (j < 32) ? j : j - 32;
            float2 cs = rope_cs(s, idx);
            val = x * cs.x + rot * cs.y;
        } else {
            val = kvb[rowb + (j - DR_)];
        }
        size_t o = (((size_t)(b * NKV + g)) * SEQ + s) * DH_ + j;
        __nv_bfloat16 hh = __float2bfloat16_rn(val);
        Khi[o] = hh;
        Klo[o] = __float2bfloat16_rn(val - __bfloat162float(hh));
    } else {
        float val = kvb[rowb + DN_ + (j - DH_)];
        size_t o = (((size_t)(b * NKV + g)) * SEQ + s) * DV_ + (j - DH_);
        __nv_bfloat16 hh = __float2bfloat16_rn(val);
        Vhi[o] = hh;
        Vlo[o] = __float2bfloat16_rn(val - __bfloat162float(hh));
    }
}

// ----------------------------- mma flash attention --------------------------
// Round-4 structure: 128 q rows / CTA, 8 warps x m16, K tiles of 64,
// single-buffered K/V loaded at tile top. Scale pre-folded into Q.
#define ABQ 128
#define ABK 64
#define QSTR 200
#define KSTR 200
#define VSTR 136
#define B_QH 0
#define B_QL 51200
#define B_KH 102400
#define B_KL 128000
#define B_VH 153600
#define B_VL 171008
#define ATTN_SMEM 188416

__global__ __launch_bounds__(256)
void attn_mma(const __nv_bfloat16* __restrict__ Qhg, const __nv_bfloat16* __restrict__ Qlg,
              const __nv_bfloat16* __restrict__ Khg, const __nv_bfloat16* __restrict__ Klg,
              const __nv_bfloat16* __restrict__ Vhg, const __nv_bfloat16* __restrict__ Vlg,
              __nv_bfloat16* __restrict__ Ohi, __nv_bfloat16* __restrict__ Olo)
{
    extern __shared__ __nv_bfloat16 sma[];
    const uint32_t sbase = smem_u32(sma);
    const int tid = threadIdx.x;
    const int lane = tid & 31;
    const int w = tid >> 5;
    // longest tiles first: reverse q-block order
    const int q0 = (gridDim.x - 1 - blockIdx.x) * ABQ;
    const int h  = blockIdx.y;
    const int b  = blockIdx.z;
    const int g  = h >> 2;

    const __nv_bfloat16* Qh = Qhg + (((size_t)(b * NH + h)) * SEQ + q0) * DH_;
    const __nv_bfloat16* Ql = Qlg + (((size_t)(b * NH + h)) * SEQ + q0) * DH_;
    const __nv_bfloat16* Kh = Khg + ((size_t)(b * NKV + g)) * SEQ * DH_;
    const __nv_bfloat16* Kl = Klg + ((size_t)(b * NKV + g)) * SEQ * DH_;
    const __nv_bfloat16* Vh = Vhg + ((size_t)(b * NKV + g)) * SEQ * DV_;
    const __nv_bfloat16* Vl = Vlg + ((size_t)(b * NKV + g)) * SEQ * DV_;

    for (int idx = tid; idx < ABQ * 24; idx += 256) {
        int r = idx / 24, c = (idx % 24) * 8;
        cp16(sbase + B_QH + (r * QSTR + c) * 2, Qh + (size_t)r * DH_ + c);
        cp16(sbase + B_QL + (r * QSTR + c) * 2, Ql + (size_t)r * DH_ + c);
    }
    CP_COMMIT();

    const int grp = lane >> 3, wi = lane & 7;
    const int a_row = ((grp & 1) << 3) + wi;
    const int a_kof = (grp >> 1) << 3;
    const int b_row = ((grp >> 1) << 3) + wi;
    const int b_kof = (grp & 1) << 3;
    const int q0w = q0 + w * 16;
    const int r_in = lane >> 2;
    const int c2   = (lane & 3) * 2;

    float o[16][4];
    #pragma unroll
    for (int i = 0; i < 16; ++i)
        #pragma unroll
        for (int j = 0; j < 4; ++j) o[i][j] = 0.f;
    float m0r = -INFINITY, m1r = -INFINITY, l0 = 0.f, l1 = 0.f;

    const int ntiles = (q0 + ABQ) / ABK;
    for (int t = 0; t < ntiles; ++t) {
        const int ks = t * ABK;
        __syncthreads();
        for (int idx = tid; idx < ABK * 24; idx += 256) {
            int r = idx / 24, c = (idx % 24) * 8;
            cp16(sbase + B_KH + (r * KSTR + c) * 2, Kh + (size_t)(ks + r) * DH_ + c);
            cp16(sbase + B_KL + (r * KSTR + c) * 2, Kl + (size_t)(ks + r) * DH_ + c);
        }
        for (int idx = tid; idx < ABK * 16; idx += 256) {
            int r = idx >> 4, c = (idx & 15) * 8;
            cp16(sbase + B_VH + (r * VSTR + c) * 2, Vh + (size_t)(ks + r) * DV_ + c);
            cp16(sbase + B_VL + (r * VSTR + c) * 2, Vl + (size_t)(ks + r) * DV_ + c);
        }
        CP_COMMIT();
        CP_WAIT(0);
        __syncthreads();

        if (ks <= q0w + 15) {
            // ---- S = Qh*Kh + Ql*Kh + Qh*Kl (scale folded into Q) ----
            float s[8][4];
            #pragma unroll
            for (int i = 0; i < 8; ++i)
                #pragma unroll
                for (int j = 0; j < 4; ++j) s[i][j] = 0.f;

            #pragma unroll
            for (int kst = 0; kst < 12; ++kst) {
                uint32_t qh[4], ql[4];
                uint32_t qoff = ((w * 16 + a_row) * QSTR + kst * 16 + a_kof) * 2;
                ldsm_x4(qh, sbase + B_QH + qoff);
                ldsm_x4(ql, sbase + B_QL + qoff);
                #pragma unroll
                for (int np = 0; np < 4; ++np) {
                    uint32_t kh[4], kl[4];
                    uint32_t koff = ((np * 16 + b_row) * KSTR + kst * 16 + b_kof) * 2;
                    ldsm_x4(kh, sbase + B_KH + koff);
                    ldsm_x4(kl, sbase + B_KL + koff);
                    mma16816(s[np*2+0], qh, kh[0], kh[1]);
                    mma16816(s[np*2+1], qh, kh[2], kh[3]);
                    mma16816(s[np*2+0], ql, kh[0], kh[1]);
                    mma16816(s[np*2+1], ql, kh[2], kh[3]);
                    mma16816(s[np*2+0], qh, kl[0], kl[1]);
                    mma16816(s[np*2+1], qh, kl[2], kl[3]);
                }
            }

            // ---- mask + row max ----
            const int row0 = q0w + r_in;
            float tm0 = -INFINITY, tm1 = -INFINITY;
            #pragma unroll
            for (int nt = 0; nt < 8; ++nt) {
                #pragma unroll
                for (int e = 0; e < 2; ++e) {
                    int col = ks + nt * 8 + c2 + e;
                    s[nt][e]     = (col <= row0)     ? s[nt][e]     : -INFINITY;
                    s[nt][e + 2] = (col <= row0 + 8) ? s[nt][e + 2] : -INFINITY;
                    tm0 = fmaxf(tm0, s[nt][e]);
                    tm1 = fmaxf(tm1, s[nt][e + 2]);
                }
            }
            tm0 = fmaxf(tm0, __shfl_xor_sync(0xffffffffu, tm0, 1));
            tm0 = fmaxf(tm0, __shfl_xor_sync(0xffffffffu, tm0, 2));
            tm1 = fmaxf(tm1, __shfl_xor_sync(0xffffffffu, tm1, 1));
            tm1 = fmaxf(tm1, __shfl_xor_sync(0xffffffffu, tm1, 2));
            float mn0 = fmaxf(m0r, tm0), mn1 = fmaxf(m1r, tm1);
            float al0 = __expf(m0r - mn0), al1 = __expf(m1r - mn1);
            m0r = mn0; m1r = mn1;

            // ---- P = exp(S - m), split hi/lo ----
            uint32_t pah[4][4], pal[4][4];
            float ps0 = 0.f, ps1 = 0.f;
            #pragma unroll
            for (int kc = 0; kc < 4; ++kc) {
                #pragma unroll
                for (int half = 0; half < 2; ++half) {
                    float* f = s[kc * 2 + half];
                    float p0 = __expf(f[0] - mn0), p1 = __expf(f[1] - mn0);
                    float p2 = __expf(f[2] - mn1), p3 = __expf(f[3] - mn1);
                    ps0 += p0 + p1; ps1 += p2 + p3;
                    __nv_bfloat162 h01 = __floats2bfloat162_rn(p0, p1);
                    __nv_bfloat162 h23 = __floats2bfloat162_rn(p2, p3);
                    float r0 = p0 - __bfloat162float(h01.x);
                    float r1 = p1 - __bfloat162float(h01.y);
                    float r2 = p2 - __bfloat162float(h23.x);
                    float r3 = p3 - __bfloat162float(h23.y);
                    __nv_bfloat162 l01 = __floats2bfloat162_rn(r0, r1);
                    __nv_bfloat162 l23 = __floats2bfloat162_rn(r2, r3);
                    pah[kc][half * 2 + 0] = *reinterpret_cast<uint32_t*>(&h01);
                    pah[kc][half * 2 + 1] = *reinterpret_cast<uint32_t*>(&h23);
                    pal[kc][half * 2 + 0] = *reinterpret_cast<uint32_t*>(&l01);
                    pal[kc][half * 2 + 1] = *reinterpret_cast<uint32_t*>(&l23);
                }
            }
            l0 = l0 * al0 + ps0;
            l1 = l1 * al1 + ps1;

            // ---- rescale O, then O += Ph*Vh + Pl*Vh + Ph*Vl ----
            #pragma unroll
            for (int nt = 0; nt < 16; ++nt) {
                o[nt][0] *= al0; o[nt][1] *= al0;
                o[nt][2] *= al1; o[nt][3] *= al1;
            }
            #pragma unroll
            for (int kc = 0; kc < 4; ++kc) {
                #pragma unroll
                for (int np = 0; np < 8; ++np) {
                    uint32_t vh[4], vl[4];
                    uint32_t voff = ((kc * 16 + ((grp & 1) << 3) + wi) * VSTR
                                     + np * 16 + ((grp >> 1) << 3)) * 2;
                    ldsm_x4_t(vh, sbase + B_VH + voff);
                    ldsm_x4_t(vl, sbase + B_VL + voff);
                    mma16816(o[np*2+0], pah[kc], vh[0], vh[1]);
                    mma16816(o[np*2+1], pah[kc], vh[2], vh[3]);
                    mma16816(o[np*2+0], pal[kc], vh[0], vh[1]);
                    mma16816(o[np*2+1], pal[kc], vh[2], vh[3]);
                    mma16816(o[np*2+0], pah[kc], vl[0], vl[1]);
                    mma16816(o[np*2+1], pah[kc], vl[2], vl[3]);
                }
            }
        }
    }

    // final normalize + write hi/lo bf16
    l0 += __shfl_xor_sync(0xffffffffu, l0, 1);
    l0 += __shfl_xor_sync(0xffffffffu, l0, 2);
    l1 += __shfl_xor_sync(0xffffffffu, l1, 1);
    l1 += __shfl_xor_sync(0xffffffffu, l1, 2);
    float inv0 = 1.0f / l0, inv1 = 1.0f / l1;

    const size_t row0 = (size_t)(b * SEQ + q0w + r_in) * (NH * DV_);
    const size_t row1 = row0 + 8 * (NH * DV_);
    #pragma unroll
    for (int np = 0; np < 16; ++np) {
        int col = h * DV_ + np * 8 + c2;
        float v0 = o[np][0] * inv0, v1 = o[np][1] * inv0;
        float v2 = o[np][2] * inv1, v3 = o[np][3] * inv1;
        __nv_bfloat162 h01 = __floats2bfloat162_rn(v0, v1);
        __nv_bfloat162 h23 = __floats2bfloat162_rn(v2, v3);
        __nv_bfloat162 l01 = __floats2bfloat162_rn(v0 - __bfloat162float(h01.x),
                                                   v1 - __bfloat162float(h01.y));
        __nv_bfloat162 l23 = __floats2bfloat162_rn(v2 - __bfloat162float(h23.x),
                                                   v3 - __bfloat162float(h23.y));
        *reinterpret_cast<__nv_bfloat162*>(&Ohi[row0 + col]) = h01;
        *reinterpret_cast<__nv_bfloat162*>(&Ohi[row1 + col]) = h23;
        *reinterpret_cast<__nv_bfloat162*>(&Olo[row0 + col]) = l01;
        *reinterpret_cast<__nv_bfloat162*>(&Olo[row1 + col]) = l23;
    }
}

// ----------------------------- host ----------------------------------------
extern "C" void kernel_launch(void* const* d_in, const int* in_sizes, int n_in,
                              void* d_out, int out_size)
{
    const float* X     = (const float*)d_in[0];
    const float* w_qa  = (const float*)d_in[2];
    const float* b_qa  = (const float*)d_in[3];
    const float* gq    = (const float*)d_in[4];
    const float* w_qb  = (const float*)d_in[5];
    const float* b_qb  = (const float*)d_in[6];
    const float* w_kva = (const float*)d_in[7];
    const float* b_kva = (const float*)d_in[8];
    const float* gkv   = (const float*)d_in[9];
    const float* w_kvb = (const float*)d_in[10];
    const float* b_kvb = (const float*)d_in[11];
    const float* w_o   = (const float*)d_in[12];
    const float* b_o   = (const float*)d_in[13];
    float* out = (float*)d_out;

    float *qa, *qb, *kva, *kvb;
    cudaGetSymbolAddress((void**)&qa,  g_qa);
    cudaGetSymbolAddress((void**)&qb,  g_qb);
    cudaGetSymbolAddress((void**)&kva, g_kva);
    cudaGetSymbolAddress((void**)&kvb, g_kvb);

    __nv_bfloat16 *Xhi, *Xlo, *QAhi, *QAlo, *KVAhi, *KVAlo, *AThi, *ATlo;
    __nv_bfloat16 *Qhi, *Qlo, *Khi, *Klo, *Vhi, *Vlo;
    __nv_bfloat16 *Wqah, *Wqal, *Wqbh, *Wqbl, *Wkvah, *Wkval, *Wkvbh, *Wkvbl, *Woh, *Wol;
    cudaGetSymbolAddress((void**)&Xhi,  g_Xhi);
    cudaGetSymbolAddress((void**)&Xlo,  g_Xlo);
    cudaGetSymbolAddress((void**)&QAhi, g_QAhi);
    cudaGetSymbolAddress((void**)&QAlo, g_QAlo);
    cudaGetSymbolAddress((void**)&KVAhi,g_KVAhi);
    cudaGetSymbolAddress((void**)&KVAlo,g_KVAlo);
    cudaGetSymbolAddress((void**)&AThi, g_AThi);
    cudaGetSymbolAddress((void**)&ATlo, g_ATlo);
    cudaGetSymbolAddress((void**)&Qhi,  g_Qhi);
    cudaGetSymbolAddress((void**)&Qlo,  g_Qlo);
    cudaGetSymbolAddress((void**)&Khi,  g_Khi);
    cudaGetSymbolAddress((void**)&Klo,  g_Klo);
    cudaGetSymbolAddress((void**)&Vhi,  g_Vhi);
    cudaGetSymbolAddress((void**)&Vlo,  g_Vlo);
    cudaGetSymbolAddress((void**)&Wqah, g_Wqa_hi);
    cudaGetSymbolAddress((void**)&Wqal, g_Wqa_lo);
    cudaGetSymbolAddress((void**)&Wqbh, g_Wqb_hi);
    cudaGetSymbolAddress((void**)&Wqbl, g_Wqb_lo);
    cudaGetSymbolAddress((void**)&Wkvah,g_Wkva_hi);
    cudaGetSymbolAddress((void**)&Wkval,g_Wkva_lo);
    cudaGetSymbolAddress((void**)&Wkvbh,g_Wkvb_hi);
    cudaGetSymbolAddress((void**)&Wkvbl,g_Wkvb_lo);
    cudaGetSymbolAddress((void**)&Woh,  g_Wo_hi);
    cudaGetSymbolAddress((void**)&Wol,  g_Wo_lo);

    cudaFuncSetAttribute(tc_gemm_bias,
        cudaFuncAttributeMaxDynamicSharedMemorySize, TC_SMEM_BYTES);
    cudaFuncSetAttribute(attn_mma,
        cudaFuncAttributeMaxDynamicSharedMemorySize, ATTN_SMEM);

    dim3 tpb(32, 8);

    // weight prep
    transpose_split<<<dim3(RQ_/32, DMODEL/32), tpb>>>(w_qa, DMODEL, RQ_, RQ_, Wqah, Wqal);
    transpose_split<<<dim3((NH*DH_)/32, RQ_/32), tpb>>>(w_qb, RQ_, NH*DH_, NH*DH_, Wqbh, Wqbl);
    transpose_split<<<dim3(KVAPAD/32, DMODEL/32), tpb>>>(w_kva, DMODEL, RKV_+DR_, KVAPAD, Wkvah, Wkval);
    transpose_split<<<dim3((NKV*(DN_+DV_))/32, RKV_/32), tpb>>>(w_kvb, RKV_, NKV*(DN_+DV_), NKV*(DN_+DV_), Wkvbh, Wkvbl);
    transpose_split<<<dim3(DMODEL/32, (NH*DV_)/32), tpb>>>(w_o, NH*DV_, DMODEL, DMODEL, Woh, Wol);

    // X split
    split_kernel<<<(ROWS*DMODEL + 255)/256, 256>>>(X, ROWS, DMODEL, DMODEL, Xhi, Xlo);

    // q path
    tc_gemm_bias<<<dim3(RQ_/128, ROWS/128), 256, TC_SMEM_BYTES>>>(
        ROWS, RQ_, DMODEL, Xhi, Xlo, Wqah, Wqal, b_qa, RQ_, qa, RQ_);
    rmsnorm_split<<<ROWS, 256>>>(qa, gq, RQ_, RQ_, QAhi, QAlo);
    tc_gemm_bias<<<dim3((NH*DH_)/128, ROWS/128), 256, TC_SMEM_BYTES>>>(
        ROWS, NH*DH_, RQ_, QAhi, QAlo, Wqbh, Wqbl, b_qb, NH*DH_, qb, NH*DH_);

    // kv path
    tc_gemm_bias<<<dim3(KVAPAD/128, ROWS/128), 256, TC_SMEM_BYTES>>>(
        ROWS, KVAPAD, DMODEL, Xhi, Xlo, Wkvah, Wkval, b_kva, RKV_+DR_, kva, KVAPAD);
    rmsnorm_split<<<ROWS, 256>>>(kva, gkv, RKV_, KVAPAD, KVAhi, KVAlo);
    tc_gemm_bias<<<dim3((NKV*(DN_+DV_))/128, ROWS/128), 256, TC_SMEM_BYTES>>>(
        ROWS, NKV*(DN_+DV_), RKV_, KVAhi, KVAlo, Wkvbh, Wkvbl, b_kvb, NKV*(DN_+DV_), kvb, NKV*(DN_+DV_));

    // rope + layout (bf16 split outputs)
    {
        int n1 = Bsz*NH*SEQ*DH_;
        rope_q_split<<<(n1 + 255)/256, 256>>>(qb, Qhi, Qlo);
        int n2 = Bsz*NKV*SEQ*(DH_+DV_);
        build_kv_split<<<(n2 + 255)/256, 256>>>(kva, kvb, Khi, Klo, Vhi, Vlo);
    }

    // attention
    attn_mma<<<dim3(SEQ/ABQ, NH, Bsz), 256, ATTN_SMEM>>>(
        Qhi, Qlo, Khi, Klo, Vhi, Vlo, AThi, ATlo);

    // out projection
    tc_gemm_bias<<<dim3(DMODEL/128, ROWS/128), 256, TC_SMEM_BYTES>>>(
        ROWS, DMODEL, NH*DV_, AThi, ATlo, Woh, Wol, b_o, DMODEL, out, DMODEL);
}